// round 4
// baseline (speedup 1.0000x reference)
#include <cuda_runtime.h>

#define NN 50000
#define NE 1600000
#define NB 196                  // ceil(NN/256)
#define SMEM_GEMM ((128*128 + 64*132)*4)

// ---------------- scratch (static __device__, no allocation) ----------------
__device__ __align__(16) float g_h[(size_t)NN * 256];     // GEMM output of current layer
__device__ __align__(16) float g_x1[(size_t)NN * 128];    // post-layer1 features
__device__ __align__(16) float g_x2[(size_t)NN * 128];    // post-layer2 features
__device__ __align__(16) float g_skip[(size_t)NN * 128];  // x @ Wskip
__device__ __align__(16) float g_as[NN * 4];
__device__ __align__(16) float g_ad[NN * 4];
__device__ __align__(16) float g_exs[(size_t)NE * 4];     // per-edge exp / alpha (CSR order)
__device__ int   g_deg[NN];
__device__ int   g_off[NN + 1];
__device__ int   g_cur[NN];
__device__ int   g_srcs[NE];                // src node per CSR slot
__device__ int   g_eids[NE];                // original edge id per CSR slot
__device__ int   g_bsum[NB];
__device__ int   g_bpre[NB];
__device__ int   g_is64;                    // edge_index dtype flag (detected per call)

__device__ __forceinline__ float lrelu(float x) { return x > 0.f ? x : 0.2f * x; }

// Read edge_index element at logical position idx (0..2*NE-1), dtype-agnostic.
__device__ __forceinline__ int edge_val(const void* ei, size_t idx) {
    int v;
    if (g_is64) v = (int)((const long long*)ei)[idx];
    else        v = ((const int*)ei)[idx];
    // clamp: converts any residual decode error into rel_err instead of a crash
    return min(max(v, 0), NN - 1);
}

// ---------------- dtype detection ----------------
// int64 little-endian with values < 2^31: every odd 32-bit word is 0.
// int32: odd words are random node indices (all-zero prob ~ (1/NN)^64).
__global__ void k_detect(const int* __restrict__ w) {
    int t = threadIdx.x;                     // one warp... use 64 threads, 2 warps
    bool zero = (w[2 * t + 1] == 0);
    __shared__ int cnt;
    if (t == 0) cnt = 0;
    __syncthreads();
    if (!zero) atomicAdd(&cnt, 1);
    __syncthreads();
    if (t == 0) g_is64 = (cnt == 0) ? 1 : 0;
}

// ---------------- CSR build ----------------
__global__ void k_zero() {
    int i = blockIdx.x * blockDim.x + threadIdx.x;
    if (i < NN) g_deg[i] = 0;
}

__global__ void k_count(const void* __restrict__ ei) {
    int e = blockIdx.x * blockDim.x + threadIdx.x;
    if (e < NE) {
        int d = edge_val(ei, (size_t)NE + e);
        atomicAdd(&g_deg[d], 1);
    }
}

__global__ void k_scan1() {
    __shared__ int s[256];
    int t = threadIdx.x;
    int i = blockIdx.x * 256 + t;
    int v = (i < NN) ? g_deg[i] : 0;
    s[t] = v;
    __syncthreads();
    for (int o = 1; o < 256; o <<= 1) {
        int add = 0;
        if (t >= o) add = s[t - o];
        __syncthreads();
        s[t] += add;
        __syncthreads();
    }
    if (i < NN) g_off[i] = s[t];            // block-local inclusive scan (temp)
    if (t == 255) g_bsum[blockIdx.x] = s[255];
}

__global__ void k_scan2() {
    __shared__ int s[256];
    int t = threadIdx.x;
    int v = (t < NB) ? g_bsum[t] : 0;
    s[t] = v;
    __syncthreads();
    for (int o = 1; o < 256; o <<= 1) {
        int add = 0;
        if (t >= o) add = s[t - o];
        __syncthreads();
        s[t] += add;
        __syncthreads();
    }
    if (t < NB) g_bpre[t] = s[t] - v;       // exclusive block prefix
}

__global__ void k_scan3() {
    int t = threadIdx.x;
    int i = blockIdx.x * 256 + t;
    if (i < NN) {
        int incl = g_off[i] + g_bpre[blockIdx.x];
        int excl = incl - g_deg[i];
        g_off[i] = excl;
        g_cur[i] = excl;
        if (i == NN - 1) g_off[NN] = incl;
    }
}

__global__ void k_scatter(const void* __restrict__ ei) {
    int e = blockIdx.x * blockDim.x + threadIdx.x;
    if (e < NE) {
        int src = edge_val(ei, e);
        int dst = edge_val(ei, (size_t)NE + e);
        int p = atomicAdd(&g_cur[dst], 1);
        g_srcs[p] = src;
        g_eids[p] = e;
    }
}

// ---------------- GEMM: C[M,ld] tile = A[M,128] @ W[128, colbase..colbase+128) ----------------
__global__ __launch_bounds__(256) void k_gemm(const float* __restrict__ A,
                                              const float* __restrict__ W,
                                              float* __restrict__ C, int M, int ldw) {
    extern __shared__ float sm[];
    float* sW = sm;                 // [128][128]
    float* sX = sm + 16384;         // [64][132]
    int tid = threadIdx.x;
    int colbase = blockIdx.y * 128;
    int r0 = blockIdx.x * 64;

#pragma unroll
    for (int i = 0; i < 16; i++) {
        int lin = i * 256 + tid;
        int wr = lin >> 5, wc4 = lin & 31;
        *(float4*)&sW[wr * 128 + wc4 * 4] =
            *(const float4*)&W[(size_t)wr * ldw + colbase + wc4 * 4];
    }
#pragma unroll
    for (int i = 0; i < 8; i++) {
        int lin = i * 256 + tid;
        int xr = lin >> 5, xc4 = lin & 31;
        int row = r0 + xr;
        float4 v = make_float4(0.f, 0.f, 0.f, 0.f);
        if (row < M) v = *(const float4*)&A[(size_t)row * 128 + xc4 * 4];
        *(float4*)&sX[xr * 132 + xc4 * 4] = v;
    }
    __syncthreads();

    int tcol = tid & 31, trow = tid >> 5;
    float acc[8][4];
#pragma unroll
    for (int r = 0; r < 8; r++)
#pragma unroll
        for (int c = 0; c < 4; c++) acc[r][c] = 0.f;

    const float* xb = sX + trow * 8 * 132;
#pragma unroll 16
    for (int k = 0; k < 128; k++) {
        float4 b = *(float4*)&sW[k * 128 + tcol * 4];
#pragma unroll
        for (int r = 0; r < 8; r++) {
            float a = xb[r * 132 + k];
            acc[r][0] += a * b.x;
            acc[r][1] += a * b.y;
            acc[r][2] += a * b.z;
            acc[r][3] += a * b.w;
        }
    }
#pragma unroll
    for (int r = 0; r < 8; r++) {
        int row = r0 + trow * 8 + r;
        if (row < M)
            *(float4*)&C[(size_t)row * ldw + colbase + tcol * 4] =
                make_float4(acc[r][0], acc[r][1], acc[r][2], acc[r][3]);
    }
}

// ---------------- per-node attention logits: as[n,h], ad[n,h] ----------------
__global__ void k_attn(const float* __restrict__ feat, const float* __restrict__ asrc,
                       const float* __restrict__ adst, int C) {
    __shared__ float sa[256], sd[256];
    int HC = 4 * C;
    if (threadIdx.x < HC) {
        sa[threadIdx.x] = asrc[threadIdx.x];
        sd[threadIdx.x] = adst[threadIdx.x];
    }
    __syncthreads();
    int id = blockIdx.x * blockDim.x + threadIdx.x;
    int n = id >> 2, h = id & 3;
    if (n >= NN) return;
    const float4* hp = (const float4*)(feat + (size_t)n * HC + h * C);
    const float4* ap = (const float4*)(sa + h * C);
    const float4* dp = (const float4*)(sd + h * C);
    float s1 = 0.f, s2 = 0.f;
    int c4 = C >> 2;
    for (int i = 0; i < c4; i++) {
        float4 v = hp[i], a = ap[i], d = dp[i];
        s1 += v.x * a.x + v.y * a.y + v.z * a.z + v.w * a.w;
        s2 += v.x * d.x + v.y * d.y + v.z * d.z + v.w * d.w;
    }
    g_as[n * 4 + h] = s1;
    g_ad[n * 4 + h] = s2;
}

// ---------------- per-dst softmax over CSR segment (warp per node) ----------------
__global__ void k_softmax(float* __restrict__ alpha_out) {
    int gt = blockIdx.x * blockDim.x + threadIdx.x;
    int n = gt >> 5;
    int lane = threadIdx.x & 31;
    if (n >= NN) return;
    int beg = g_off[n], end = g_off[n + 1];
    float4 adn = *(float4*)&g_ad[n * 4];

    float4 mx = make_float4(-1e30f, -1e30f, -1e30f, -1e30f);
    for (int j = beg + lane; j < end; j += 32) {
        int s = g_srcs[j];
        float4 a = *(float4*)&g_as[s * 4];
        mx.x = fmaxf(mx.x, lrelu(a.x + adn.x));
        mx.y = fmaxf(mx.y, lrelu(a.y + adn.y));
        mx.z = fmaxf(mx.z, lrelu(a.z + adn.z));
        mx.w = fmaxf(mx.w, lrelu(a.w + adn.w));
    }
#pragma unroll
    for (int o = 16; o > 0; o >>= 1) {
        mx.x = fmaxf(mx.x, __shfl_xor_sync(0xffffffffu, mx.x, o));
        mx.y = fmaxf(mx.y, __shfl_xor_sync(0xffffffffu, mx.y, o));
        mx.z = fmaxf(mx.z, __shfl_xor_sync(0xffffffffu, mx.z, o));
        mx.w = fmaxf(mx.w, __shfl_xor_sync(0xffffffffu, mx.w, o));
    }
    float4 sm = make_float4(0.f, 0.f, 0.f, 0.f);
    for (int j = beg + lane; j < end; j += 32) {
        int s = g_srcs[j];
        float4 a = *(float4*)&g_as[s * 4];
        float4 ex;
        ex.x = __expf(lrelu(a.x + adn.x) - mx.x);
        ex.y = __expf(lrelu(a.y + adn.y) - mx.y);
        ex.z = __expf(lrelu(a.z + adn.z) - mx.z);
        ex.w = __expf(lrelu(a.w + adn.w) - mx.w);
        *(float4*)&g_exs[(size_t)j * 4] = ex;
        sm.x += ex.x; sm.y += ex.y; sm.z += ex.z; sm.w += ex.w;
    }
#pragma unroll
    for (int o = 16; o > 0; o >>= 1) {
        sm.x += __shfl_xor_sync(0xffffffffu, sm.x, o);
        sm.y += __shfl_xor_sync(0xffffffffu, sm.y, o);
        sm.z += __shfl_xor_sync(0xffffffffu, sm.z, o);
        sm.w += __shfl_xor_sync(0xffffffffu, sm.w, o);
    }
    float4 inv;
    inv.x = 1.f / (sm.x + 1e-16f);
    inv.y = 1.f / (sm.y + 1e-16f);
    inv.z = 1.f / (sm.z + 1e-16f);
    inv.w = 1.f / (sm.w + 1e-16f);
    for (int j = beg + lane; j < end; j += 32) {
        float4 ex = *(float4*)&g_exs[(size_t)j * 4];
        float4 al = make_float4(ex.x * inv.x, ex.y * inv.y, ex.z * inv.z, ex.w * inv.w);
        *(float4*)&g_exs[(size_t)j * 4] = al;                  // normalized, CSR order
        int e0 = g_eids[j];
        *(float4*)&alpha_out[(size_t)e0 * 4] = al;             // output alpha
    }
}

// ---------------- aggregation layers 1/2 (128 ch) + bias/ELU/LN[/skip] ----------------
__global__ __launch_bounds__(128) void k_agg12(const float* __restrict__ feat,
                                               const float* __restrict__ bias,
                                               const float* __restrict__ lnw,
                                               const float* __restrict__ lnb,
                                               const float* __restrict__ skip,
                                               const float* __restrict__ bskip,
                                               float* __restrict__ outp) {
    int n = blockIdx.x;
    int tid = threadIdx.x;
    int h = tid >> 5;
    __shared__ int ss[128];
    __shared__ float sal[128 * 4];
    __shared__ float red[128];
    int beg = g_off[n], end = g_off[n + 1];
    float acc = 0.f;
    for (int c0 = beg; c0 < end; c0 += 128) {
        int m = min(128, end - c0);
        if (tid < m) {
            ss[tid] = g_srcs[c0 + tid];
            *(float4*)&sal[tid * 4] = *(float4*)&g_exs[(size_t)(c0 + tid) * 4];
        }
        __syncthreads();
#pragma unroll 4
        for (int j = 0; j < m; j++)
            acc += sal[j * 4 + h] * feat[(size_t)ss[j] * 128 + tid];
        __syncthreads();
    }
    float v = acc + bias[tid];
    v = v > 0.f ? v : expm1f(v);              // ELU
    red[tid] = v;
    __syncthreads();
#pragma unroll
    for (int s = 64; s > 0; s >>= 1) {
        if (tid < s) red[tid] += red[tid + s];
        __syncthreads();
    }
    float mu = red[0] * (1.f / 128.f);
    __syncthreads();
    float d = v - mu;
    red[tid] = d * d;
    __syncthreads();
#pragma unroll
    for (int s = 64; s > 0; s >>= 1) {
        if (tid < s) red[tid] += red[tid + s];
        __syncthreads();
    }
    float var = red[0] * (1.f / 128.f);
    float y = d * rsqrtf(var + 1e-5f) * lnw[tid] + lnb[tid];
    if (skip) y += skip[(size_t)n * 128 + tid] + bskip[tid];
    outp[(size_t)n * 128 + tid] = y;
}

// ---------------- aggregation layer 3 (256 ch) + head-mean + bias -> d_out ----------------
__global__ __launch_bounds__(256) void k_agg3(const float* __restrict__ feat,
                                              const float* __restrict__ b3,
                                              float* __restrict__ outp) {
    int n = blockIdx.x;
    int tid = threadIdx.x;
    int h = tid >> 6;
    __shared__ int ss[128];
    __shared__ float sal[128 * 4];
    __shared__ float red[256];
    int beg = g_off[n], end = g_off[n + 1];
    float acc = 0.f;
    for (int c0 = beg; c0 < end; c0 += 128) {
        int m = min(128, end - c0);
        if (tid < m) {
            ss[tid] = g_srcs[c0 + tid];
            *(float4*)&sal[tid * 4] = *(float4*)&g_exs[(size_t)(c0 + tid) * 4];
        }
        __syncthreads();
#pragma unroll 4
        for (int j = 0; j < m; j++)
            acc += sal[j * 4 + h] * feat[(size_t)ss[j] * 256 + tid];
        __syncthreads();
    }
    red[tid] = acc;
    __syncthreads();
    if (tid < 64) {
        float v = (red[tid] + red[tid + 64] + red[tid + 128] + red[tid + 192]) * 0.25f + b3[tid];
        outp[(size_t)n * 64 + tid] = v;
    }
}

// ---------------- host ----------------
extern "C" void kernel_launch(void* const* d_in, const int* in_sizes, int n_in,
                              void* d_out, int out_size) {
    const float* x    = (const float*)d_in[0];
    const void*  ei   = d_in[1];
    const float* W1   = (const float*)d_in[2];
    const float* as1  = (const float*)d_in[3];
    const float* ad1  = (const float*)d_in[4];
    const float* b1   = (const float*)d_in[5];
    const float* ln1w = (const float*)d_in[6];
    const float* ln1b = (const float*)d_in[7];
    const float* Wsk  = (const float*)d_in[8];
    const float* bsk  = (const float*)d_in[9];
    const float* W2   = (const float*)d_in[10];
    const float* as2  = (const float*)d_in[11];
    const float* ad2  = (const float*)d_in[12];
    const float* b2   = (const float*)d_in[13];
    const float* ln2w = (const float*)d_in[14];
    const float* ln2b = (const float*)d_in[15];
    const float* W3   = (const float*)d_in[16];
    const float* as3  = (const float*)d_in[17];
    const float* ad3  = (const float*)d_in[18];
    const float* b3   = (const float*)d_in[19];

    float* out = (float*)d_out;
    float* A1 = out + (size_t)NN * 64;
    float* A2 = A1 + (size_t)NE * 4;
    float* A3 = A2 + (size_t)NE * 4;

    cudaFuncSetAttribute((const void*)k_gemm,
                         cudaFuncAttributeMaxDynamicSharedMemorySize, SMEM_GEMM);

    void *ph, *px1, *px2, *psk;
    cudaGetSymbolAddress(&ph, g_h);
    cudaGetSymbolAddress(&px1, g_x1);
    cudaGetSymbolAddress(&px2, g_x2);
    cudaGetSymbolAddress(&psk, g_skip);
    float* fh  = (float*)ph;
    float* fx1 = (float*)px1;
    float* fx2 = (float*)px2;
    float* fsk = (float*)psk;

    // CSR build (per call; edge_index is an input)
    k_detect<<<1, 64>>>((const int*)ei);
    k_zero<<<NB, 256>>>();
    k_count<<<(NE + 255) / 256, 256>>>(ei);
    k_scan1<<<NB, 256>>>();
    k_scan2<<<1, 256>>>();
    k_scan3<<<NB, 256>>>();
    k_scatter<<<(NE + 255) / 256, 256>>>(ei);

    dim3 ggrid((NN + 63) / 64, 1);
    // ---- layer 1 ----
    k_gemm<<<ggrid, 256, SMEM_GEMM>>>(x, W1, fh, NN, 128);
    k_gemm<<<ggrid, 256, SMEM_GEMM>>>(x, Wsk, fsk, NN, 128);
    k_attn<<<(NN * 4 + 255) / 256, 256>>>(fh, as1, ad1, 32);
    k_softmax<<<(NN + 7) / 8, 256>>>(A1);
    k_agg12<<<NN, 128>>>(fh, b1, ln1w, ln1b, fsk, bsk, fx1);
    // ---- layer 2 ----
    k_gemm<<<ggrid, 256, SMEM_GEMM>>>(fx1, W2, fh, NN, 128);
    k_attn<<<(NN * 4 + 255) / 256, 256>>>(fh, as2, ad2, 32);
    k_softmax<<<(NN + 7) / 8, 256>>>(A2);
    k_agg12<<<NN, 128>>>(fh, b2, ln2w, ln2b, nullptr, nullptr, fx2);
    // ---- layer 3 ----
    dim3 ggrid3((NN + 63) / 64, 2);
    k_gemm<<<ggrid3, 256, SMEM_GEMM>>>(fx2, W3, fh, NN, 256);
    k_attn<<<(NN * 4 + 255) / 256, 256>>>(fh, as3, ad3, 64);
    k_softmax<<<(NN + 7) / 8, 256>>>(A3);
    k_agg3<<<NN, 256>>>(fh, b3, out);
}

// round 5
// speedup vs baseline: 1.4298x; 1.4298x over previous
#include <cuda_runtime.h>

#define NN 50000
#define NE 1600000
#define NB 196                  // ceil(NN/256)
#define SMEM_GEMM ((128*128 + 64*132)*4)
#define FULLMASK 0xffffffffu

// ---------------- scratch (static __device__, no allocation) ----------------
__device__ __align__(16) float g_h[(size_t)NN * 256];     // GEMM output of current layer
__device__ __align__(16) float g_x1[(size_t)NN * 128];    // post-layer1 features
__device__ __align__(16) float g_x2[(size_t)NN * 128];    // post-layer2 features
__device__ __align__(16) float g_skip[(size_t)NN * 128];  // x @ Wskip
__device__ __align__(16) float g_as[NN * 4];
__device__ __align__(16) float g_ad[NN * 4];
__device__ __align__(16) float g_exs[(size_t)NE * 4];     // per-edge exp->alpha (CSR order)
__device__ int   g_deg[NN];
__device__ int   g_off[NN + 1];
__device__ int   g_cur[NN];
__device__ int   g_srcs[NE];                // src node per CSR slot
__device__ int   g_pos[NE];                 // edge id -> CSR slot
__device__ int   g_bsum[NB];
__device__ int   g_bpre[NB];
__device__ int   g_is64;

__device__ __forceinline__ float lrelu(float x) { return x > 0.f ? x : 0.2f * x; }

__device__ __forceinline__ int edge_val(const void* ei, size_t idx) {
    int v;
    if (g_is64) v = (int)((const long long*)ei)[idx];
    else        v = ((const int*)ei)[idx];
    return min(max(v, 0), NN - 1);
}

// ---------------- dtype detection ----------------
__global__ void k_detect(const int* __restrict__ w) {
    int t = threadIdx.x;
    bool zero = (w[2 * t + 1] == 0);
    __shared__ int cnt;
    if (t == 0) cnt = 0;
    __syncthreads();
    if (!zero) atomicAdd(&cnt, 1);
    __syncthreads();
    if (t == 0) g_is64 = (cnt == 0) ? 1 : 0;
}

// ---------------- CSR build ----------------
__global__ void k_zero() {
    int i = blockIdx.x * blockDim.x + threadIdx.x;
    if (i < NN) g_deg[i] = 0;
}

__global__ void k_count(const void* __restrict__ ei) {
    int e = blockIdx.x * blockDim.x + threadIdx.x;
    if (e < NE) atomicAdd(&g_deg[edge_val(ei, (size_t)NE + e)], 1);
}

__global__ void k_scan1() {
    __shared__ int s[256];
    int t = threadIdx.x;
    int i = blockIdx.x * 256 + t;
    int v = (i < NN) ? g_deg[i] : 0;
    s[t] = v;
    __syncthreads();
    for (int o = 1; o < 256; o <<= 1) {
        int add = 0;
        if (t >= o) add = s[t - o];
        __syncthreads();
        s[t] += add;
        __syncthreads();
    }
    if (i < NN) g_off[i] = s[t];
    if (t == 255) g_bsum[blockIdx.x] = s[255];
}

__global__ void k_scan2() {
    __shared__ int s[256];
    int t = threadIdx.x;
    int v = (t < NB) ? g_bsum[t] : 0;
    s[t] = v;
    __syncthreads();
    for (int o = 1; o < 256; o <<= 1) {
        int add = 0;
        if (t >= o) add = s[t - o];
        __syncthreads();
        s[t] += add;
        __syncthreads();
    }
    if (t < NB) g_bpre[t] = s[t] - v;
}

__global__ void k_scan3() {
    int t = threadIdx.x;
    int i = blockIdx.x * 256 + t;
    if (i < NN) {
        int incl = g_off[i] + g_bpre[blockIdx.x];
        int excl = incl - g_deg[i];
        g_off[i] = excl;
        g_cur[i] = excl;
        if (i == NN - 1) g_off[NN] = incl;
    }
}

__global__ void k_scatter(const void* __restrict__ ei) {
    int e = blockIdx.x * blockDim.x + threadIdx.x;
    if (e < NE) {
        int src = edge_val(ei, e);
        int dst = edge_val(ei, (size_t)NE + e);
        int p = atomicAdd(&g_cur[dst], 1);
        g_srcs[p] = src;
        g_pos[e] = p;
    }
}

// ---------------- GEMM: C tile = A[M,128] @ W[128, colbase..+128) ----------------
__device__ __forceinline__ void gemm_core(const float* sW, const float* sX,
                                          float* __restrict__ C, int M, int ldw,
                                          int colbase, int r0, int tid) {
    int tcol = tid & 31, trow = tid >> 5;
    float acc[8][4];
#pragma unroll
    for (int r = 0; r < 8; r++)
#pragma unroll
        for (int c = 0; c < 4; c++) acc[r][c] = 0.f;

    const float* xb = sX + trow * 8 * 132;
#pragma unroll 16
    for (int k = 0; k < 128; k++) {
        float4 b = *(const float4*)&sW[k * 128 + tcol * 4];
#pragma unroll
        for (int r = 0; r < 8; r++) {
            float a = xb[r * 132 + k];
            acc[r][0] += a * b.x;
            acc[r][1] += a * b.y;
            acc[r][2] += a * b.z;
            acc[r][3] += a * b.w;
        }
    }
#pragma unroll
    for (int r = 0; r < 8; r++) {
        int row = r0 + trow * 8 + r;
        if (row < M)
            *(float4*)&C[(size_t)row * ldw + colbase + tcol * 4] =
                make_float4(acc[r][0], acc[r][1], acc[r][2], acc[r][3]);
    }
}

__device__ __forceinline__ void load_w(float* sW, const float* __restrict__ W,
                                       int ldw, int colbase, int tid) {
#pragma unroll
    for (int i = 0; i < 16; i++) {
        int lin = i * 256 + tid;
        int wr = lin >> 5, wc4 = lin & 31;
        *(float4*)&sW[wr * 128 + wc4 * 4] =
            *(const float4*)&W[(size_t)wr * ldw + colbase + wc4 * 4];
    }
}

__global__ __launch_bounds__(256) void k_gemm(const float* __restrict__ A,
                                              const float* __restrict__ W,
                                              float* __restrict__ C, int M, int ldw) {
    extern __shared__ float sm[];
    float* sW = sm;
    float* sX = sm + 16384;
    int tid = threadIdx.x;
    int colbase = blockIdx.y * 128;
    int r0 = blockIdx.x * 64;

    load_w(sW, W, ldw, colbase, tid);
#pragma unroll
    for (int i = 0; i < 8; i++) {
        int lin = i * 256 + tid;
        int xr = lin >> 5, xc4 = lin & 31;
        int row = r0 + xr;
        float4 v = make_float4(0.f, 0.f, 0.f, 0.f);
        if (row < M) v = *(const float4*)&A[(size_t)row * 128 + xc4 * 4];
        *(float4*)&sX[xr * 132 + xc4 * 4] = v;
    }
    __syncthreads();
    gemm_core(sW, sX, C, M, ldw, colbase, r0, tid);
}

// two GEMMs sharing A (layer 1: W1 and Wskip)
__global__ __launch_bounds__(256) void k_gemm2(const float* __restrict__ A,
                                               const float* __restrict__ W1,
                                               float* __restrict__ C1,
                                               const float* __restrict__ W2,
                                               float* __restrict__ C2, int M) {
    extern __shared__ float sm[];
    float* sW = sm;
    float* sX = sm + 16384;
    int tid = threadIdx.x;
    int r0 = blockIdx.x * 64;

    load_w(sW, W1, 128, 0, tid);
#pragma unroll
    for (int i = 0; i < 8; i++) {
        int lin = i * 256 + tid;
        int xr = lin >> 5, xc4 = lin & 31;
        int row = r0 + xr;
        float4 v = make_float4(0.f, 0.f, 0.f, 0.f);
        if (row < M) v = *(const float4*)&A[(size_t)row * 128 + xc4 * 4];
        *(float4*)&sX[xr * 132 + xc4 * 4] = v;
    }
    __syncthreads();
    gemm_core(sW, sX, C1, M, 128, 0, r0, tid);
    __syncthreads();
    load_w(sW, W2, 128, 0, tid);
    __syncthreads();
    gemm_core(sW, sX, C2, M, 128, 0, r0, tid);
}

// ---------------- per-node attention logits ----------------
__global__ void k_attn(const float* __restrict__ feat, const float* __restrict__ asrc,
                       const float* __restrict__ adst, int C) {
    __shared__ float sa[256], sd[256];
    int HC = 4 * C;
    if (threadIdx.x < HC) {
        sa[threadIdx.x] = asrc[threadIdx.x];
        sd[threadIdx.x] = adst[threadIdx.x];
    }
    __syncthreads();
    int id = blockIdx.x * blockDim.x + threadIdx.x;
    int n = id >> 2, h = id & 3;
    if (n >= NN) return;
    const float4* hp = (const float4*)(feat + (size_t)n * HC + h * C);
    const float4* ap = (const float4*)(sa + h * C);
    const float4* dp = (const float4*)(sd + h * C);
    float s1 = 0.f, s2 = 0.f;
    int c4 = C >> 2;
    for (int i = 0; i < c4; i++) {
        float4 v = hp[i], a = ap[i], d = dp[i];
        s1 += v.x * a.x + v.y * a.y + v.z * a.z + v.w * a.w;
        s2 += v.x * d.x + v.y * d.y + v.z * d.z + v.w * d.w;
    }
    g_as[n * 4 + h] = s1;
    g_ad[n * 4 + h] = s2;
}

// ---------------- fused softmax + aggregation, warp per node ----------------
__device__ __forceinline__ void softmax_phase(int beg, int end, int lane, float4 adn,
                                              float4& inv) {
    float4 mx = make_float4(-1e30f, -1e30f, -1e30f, -1e30f);
    for (int j = beg + lane; j < end; j += 32) {
        int s = g_srcs[j];
        float4 a = *(const float4*)&g_as[s * 4];
        mx.x = fmaxf(mx.x, lrelu(a.x + adn.x));
        mx.y = fmaxf(mx.y, lrelu(a.y + adn.y));
        mx.z = fmaxf(mx.z, lrelu(a.z + adn.z));
        mx.w = fmaxf(mx.w, lrelu(a.w + adn.w));
    }
#pragma unroll
    for (int o = 16; o > 0; o >>= 1) {
        mx.x = fmaxf(mx.x, __shfl_xor_sync(FULLMASK, mx.x, o));
        mx.y = fmaxf(mx.y, __shfl_xor_sync(FULLMASK, mx.y, o));
        mx.z = fmaxf(mx.z, __shfl_xor_sync(FULLMASK, mx.z, o));
        mx.w = fmaxf(mx.w, __shfl_xor_sync(FULLMASK, mx.w, o));
    }
    float4 sm = make_float4(0.f, 0.f, 0.f, 0.f);
    float4* EX = (float4*)g_exs;
    for (int j = beg + lane; j < end; j += 32) {
        int s = g_srcs[j];
        float4 a = *(const float4*)&g_as[s * 4];
        float4 ex;
        ex.x = __expf(lrelu(a.x + adn.x) - mx.x);
        ex.y = __expf(lrelu(a.y + adn.y) - mx.y);
        ex.z = __expf(lrelu(a.z + adn.z) - mx.z);
        ex.w = __expf(lrelu(a.w + adn.w) - mx.w);
        EX[j] = ex;
        sm.x += ex.x; sm.y += ex.y; sm.z += ex.z; sm.w += ex.w;
    }
#pragma unroll
    for (int o = 16; o > 0; o >>= 1) {
        sm.x += __shfl_xor_sync(FULLMASK, sm.x, o);
        sm.y += __shfl_xor_sync(FULLMASK, sm.y, o);
        sm.z += __shfl_xor_sync(FULLMASK, sm.z, o);
        sm.w += __shfl_xor_sync(FULLMASK, sm.w, o);
    }
    inv.x = 1.f / (sm.x + 1e-16f);
    inv.y = 1.f / (sm.y + 1e-16f);
    inv.z = 1.f / (sm.z + 1e-16f);
    inv.w = 1.f / (sm.w + 1e-16f);
    __syncwarp();
    for (int j = beg + lane; j < end; j += 32) {       // normalize in place
        float4 ex = EX[j];
        ex.x *= inv.x; ex.y *= inv.y; ex.z *= inv.z; ex.w *= inv.w;
        EX[j] = ex;
    }
    __syncwarp();
}

__device__ __forceinline__ float warp_sum(float v) {
#pragma unroll
    for (int o = 16; o > 0; o >>= 1) v += __shfl_xor_sync(FULLMASK, v, o);
    return v;
}

// layers 1/2: 128 channels, epilogue bias+ELU+LN[+skip]
__global__ __launch_bounds__(256) void k_softagg12(const float* __restrict__ feat,
                                                   const float* __restrict__ bias,
                                                   const float* __restrict__ lnw,
                                                   const float* __restrict__ lnb,
                                                   const float* __restrict__ skip,
                                                   const float* __restrict__ bskip,
                                                   float* __restrict__ outp) {
    int n = blockIdx.x * 8 + (threadIdx.x >> 5);
    int lane = threadIdx.x & 31;
    if (n >= NN) return;
    int beg = g_off[n], end = g_off[n + 1];
    float4 adn = *(const float4*)&g_ad[n * 4];
    float4 inv;
    softmax_phase(beg, end, lane, adn, inv);

    // aggregate: lane owns channels 4*lane..4*lane+3 (head = lane>>3)
    int h = lane >> 3;
    const float4* F = (const float4*)feat;
    float4 acc = make_float4(0.f, 0.f, 0.f, 0.f);
    int j = beg;
    for (; j + 4 <= end; j += 4) {
        int s0 = g_srcs[j], s1 = g_srcs[j + 1], s2 = g_srcs[j + 2], s3 = g_srcs[j + 3];
        float a0 = g_exs[(size_t)j * 4 + h];
        float a1 = g_exs[(size_t)(j + 1) * 4 + h];
        float a2 = g_exs[(size_t)(j + 2) * 4 + h];
        float a3 = g_exs[(size_t)(j + 3) * 4 + h];
        float4 f0 = F[(size_t)s0 * 32 + lane];
        float4 f1 = F[(size_t)s1 * 32 + lane];
        float4 f2 = F[(size_t)s2 * 32 + lane];
        float4 f3 = F[(size_t)s3 * 32 + lane];
        acc.x += a0 * f0.x + a1 * f1.x + a2 * f2.x + a3 * f3.x;
        acc.y += a0 * f0.y + a1 * f1.y + a2 * f2.y + a3 * f3.y;
        acc.z += a0 * f0.z + a1 * f1.z + a2 * f2.z + a3 * f3.z;
        acc.w += a0 * f0.w + a1 * f1.w + a2 * f2.w + a3 * f3.w;
    }
    for (; j < end; j++) {
        int s = g_srcs[j];
        float a = g_exs[(size_t)j * 4 + h];
        float4 f = F[(size_t)s * 32 + lane];
        acc.x += a * f.x; acc.y += a * f.y; acc.z += a * f.z; acc.w += a * f.w;
    }

    float4 b4 = ((const float4*)bias)[lane];
    float4 v = make_float4(acc.x + b4.x, acc.y + b4.y, acc.z + b4.z, acc.w + b4.w);
    v.x = v.x > 0.f ? v.x : expm1f(v.x);
    v.y = v.y > 0.f ? v.y : expm1f(v.y);
    v.z = v.z > 0.f ? v.z : expm1f(v.z);
    v.w = v.w > 0.f ? v.w : expm1f(v.w);
    float mu = warp_sum(v.x + v.y + v.z + v.w) * (1.f / 128.f);
    float4 d = make_float4(v.x - mu, v.y - mu, v.z - mu, v.w - mu);
    float var = warp_sum(d.x * d.x + d.y * d.y + d.z * d.z + d.w * d.w) * (1.f / 128.f);
    float rstd = rsqrtf(var + 1e-5f);
    float4 w4 = ((const float4*)lnw)[lane];
    float4 lb = ((const float4*)lnb)[lane];
    float4 y = make_float4(d.x * rstd * w4.x + lb.x, d.y * rstd * w4.y + lb.y,
                           d.z * rstd * w4.z + lb.z, d.w * rstd * w4.w + lb.w);
    if (skip) {
        float4 sk = ((const float4*)skip)[(size_t)n * 32 + lane];
        float4 bs = ((const float4*)bskip)[lane];
        y.x += sk.x + bs.x; y.y += sk.y + bs.y; y.z += sk.z + bs.z; y.w += sk.w + bs.w;
    }
    ((float4*)outp)[(size_t)n * 32 + lane] = y;
}

// layer 3: 256 channels, epilogue head-mean + bias -> out[N,64]
__global__ __launch_bounds__(256) void k_softagg3(const float* __restrict__ feat,
                                                  const float* __restrict__ b3,
                                                  float* __restrict__ outp) {
    int n = blockIdx.x * 8 + (threadIdx.x >> 5);
    int lane = threadIdx.x & 31;
    if (n >= NN) return;
    int beg = g_off[n], end = g_off[n + 1];
    float4 adn = *(const float4*)&g_ad[n * 4];
    float4 inv;
    softmax_phase(beg, end, lane, adn, inv);

    // channels: lane -> 4*lane..4*lane+3 (head lane>>4) and 128+4*lane.. (head 2+(lane>>4))
    int hlo = lane >> 4;
    const float4* F = (const float4*)feat;
    float4 acc0 = make_float4(0.f, 0.f, 0.f, 0.f);
    float4 acc1 = make_float4(0.f, 0.f, 0.f, 0.f);
    int j = beg;
    for (; j + 2 <= end; j += 2) {
        int s0 = g_srcs[j], s1 = g_srcs[j + 1];
        float al0 = g_exs[(size_t)j * 4 + hlo];
        float ah0 = g_exs[(size_t)j * 4 + 2 + hlo];
        float al1 = g_exs[(size_t)(j + 1) * 4 + hlo];
        float ah1 = g_exs[(size_t)(j + 1) * 4 + 2 + hlo];
        float4 f00 = F[(size_t)s0 * 64 + lane];
        float4 f01 = F[(size_t)s0 * 64 + 32 + lane];
        float4 f10 = F[(size_t)s1 * 64 + lane];
        float4 f11 = F[(size_t)s1 * 64 + 32 + lane];
        acc0.x += al0 * f00.x + al1 * f10.x;
        acc0.y += al0 * f00.y + al1 * f10.y;
        acc0.z += al0 * f00.z + al1 * f10.z;
        acc0.w += al0 * f00.w + al1 * f10.w;
        acc1.x += ah0 * f01.x + ah1 * f11.x;
        acc1.y += ah0 * f01.y + ah1 * f11.y;
        acc1.z += ah0 * f01.z + ah1 * f11.z;
        acc1.w += ah0 * f01.w + ah1 * f11.w;
    }
    for (; j < end; j++) {
        int s = g_srcs[j];
        float al = g_exs[(size_t)j * 4 + hlo];
        float ah = g_exs[(size_t)j * 4 + 2 + hlo];
        float4 f0 = F[(size_t)s * 64 + lane];
        float4 f1 = F[(size_t)s * 64 + 32 + lane];
        acc0.x += al * f0.x; acc0.y += al * f0.y; acc0.z += al * f0.z; acc0.w += al * f0.w;
        acc1.x += ah * f1.x; acc1.y += ah * f1.y; acc1.z += ah * f1.z; acc1.w += ah * f1.w;
    }
    // head mean: out[4c..4c+3] = (acc0[c] + acc0[c+16] + acc1[c] + acc1[c+16]) / 4
    acc0.x += __shfl_down_sync(FULLMASK, acc0.x, 16);
    acc0.y += __shfl_down_sync(FULLMASK, acc0.y, 16);
    acc0.z += __shfl_down_sync(FULLMASK, acc0.z, 16);
    acc0.w += __shfl_down_sync(FULLMASK, acc0.w, 16);
    acc1.x += __shfl_down_sync(FULLMASK, acc1.x, 16);
    acc1.y += __shfl_down_sync(FULLMASK, acc1.y, 16);
    acc1.z += __shfl_down_sync(FULLMASK, acc1.z, 16);
    acc1.w += __shfl_down_sync(FULLMASK, acc1.w, 16);
    if (lane < 16) {
        float4 bb = ((const float4*)b3)[lane];
        float4 r;
        r.x = (acc0.x + acc1.x) * 0.25f + bb.x;
        r.y = (acc0.y + acc1.y) * 0.25f + bb.y;
        r.z = (acc0.z + acc1.z) * 0.25f + bb.z;
        r.w = (acc0.w + acc1.w) * 0.25f + bb.w;
        ((float4*)outp)[(size_t)n * 16 + lane] = r;
    }
}

// alpha output: coalesced write in original edge order
__global__ void k_alpha(float* __restrict__ alpha_out) {
    int e = blockIdx.x * blockDim.x + threadIdx.x;
    if (e < NE) {
        int p = g_pos[e];
        ((float4*)alpha_out)[e] = ((const float4*)g_exs)[p];
    }
}

// ---------------- host ----------------
extern "C" void kernel_launch(void* const* d_in, const int* in_sizes, int n_in,
                              void* d_out, int out_size) {
    const float* x    = (const float*)d_in[0];
    const void*  ei   = d_in[1];
    const float* W1   = (const float*)d_in[2];
    const float* as1  = (const float*)d_in[3];
    const float* ad1  = (const float*)d_in[4];
    const float* b1   = (const float*)d_in[5];
    const float* ln1w = (const float*)d_in[6];
    const float* ln1b = (const float*)d_in[7];
    const float* Wsk  = (const float*)d_in[8];
    const float* bsk  = (const float*)d_in[9];
    const float* W2   = (const float*)d_in[10];
    const float* as2  = (const float*)d_in[11];
    const float* ad2  = (const float*)d_in[12];
    const float* b2   = (const float*)d_in[13];
    const float* ln2w = (const float*)d_in[14];
    const float* ln2b = (const float*)d_in[15];
    const float* W3   = (const float*)d_in[16];
    const float* as3  = (const float*)d_in[17];
    const float* ad3  = (const float*)d_in[18];
    const float* b3   = (const float*)d_in[19];

    float* out = (float*)d_out;
    float* A1 = out + (size_t)NN * 64;
    float* A2 = A1 + (size_t)NE * 4;
    float* A3 = A2 + (size_t)NE * 4;

    cudaFuncSetAttribute((const void*)k_gemm,
                         cudaFuncAttributeMaxDynamicSharedMemorySize, SMEM_GEMM);
    cudaFuncSetAttribute((const void*)k_gemm2,
                         cudaFuncAttributeMaxDynamicSharedMemorySize, SMEM_GEMM);

    void *ph, *px1, *px2, *psk;
    cudaGetSymbolAddress(&ph, g_h);
    cudaGetSymbolAddress(&px1, g_x1);
    cudaGetSymbolAddress(&px2, g_x2);
    cudaGetSymbolAddress(&psk, g_skip);
    float* fh  = (float*)ph;
    float* fx1 = (float*)px1;
    float* fx2 = (float*)px2;
    float* fsk = (float*)psk;

    // CSR build
    k_detect<<<1, 64>>>((const int*)ei);
    k_zero<<<NB, 256>>>();
    k_count<<<(NE + 255) / 256, 256>>>(ei);
    k_scan1<<<NB, 256>>>();
    k_scan2<<<1, 256>>>();
    k_scan3<<<NB, 256>>>();
    k_scatter<<<(NE + 255) / 256, 256>>>(ei);

    dim3 ggrid((NN + 63) / 64, 1);
    int agrid = (NN + 7) / 8;
    int egrid = (NE + 255) / 256;
    // ---- layer 1 ----
    k_gemm2<<<ggrid, 256, SMEM_GEMM>>>(x, W1, fh, Wsk, fsk, NN);
    k_attn<<<(NN * 4 + 255) / 256, 256>>>(fh, as1, ad1, 32);
    k_softagg12<<<agrid, 256>>>(fh, b1, ln1w, ln1b, fsk, bsk, fx1);
    k_alpha<<<egrid, 256>>>(A1);
    // ---- layer 2 ----
    k_gemm<<<ggrid, 256, SMEM_GEMM>>>(fx1, W2, fh, NN, 128);
    k_attn<<<(NN * 4 + 255) / 256, 256>>>(fh, as2, ad2, 32);
    k_softagg12<<<agrid, 256>>>(fh, b2, ln2w, ln2b, nullptr, nullptr, fx2);
    k_alpha<<<egrid, 256>>>(A2);
    // ---- layer 3 ----
    dim3 ggrid3((NN + 63) / 64, 2);
    k_gemm<<<ggrid3, 256, SMEM_GEMM>>>(fx2, W3, fh, NN, 256);
    k_attn<<<(NN * 4 + 255) / 256, 256>>>(fh, as3, ad3, 64);
    k_softagg3<<<agrid, 256>>>(fh, b3, out);
    k_alpha<<<egrid, 256>>>(A3);
}

// round 6
// speedup vs baseline: 1.4506x; 1.0145x over previous
#include <cuda_runtime.h>

#define NN 50000
#define NE 1600000
#define NB 196                  // ceil(NN/256)
#define SMEM_GEMM ((128*128 + 128*66)*4)
#define FULLMASK 0xffffffffu

// ---------------- scratch (static __device__, no allocation) ----------------
__device__ __align__(16) float g_h[(size_t)NN * 256];
__device__ __align__(16) float g_x1[(size_t)NN * 128];
__device__ __align__(16) float g_x2[(size_t)NN * 128];
__device__ __align__(16) float g_skip[(size_t)NN * 128];
__device__ __align__(16) float g_as[NN * 4];
__device__ __align__(16) float g_ad[NN * 4];
__device__ __align__(16) float g_inv[NN * 4];
__device__ __align__(16) float g_exs[(size_t)NE * 4];   // unnormalized exp (CSR order)
__device__ int   g_deg[NN];
__device__ int   g_off[NN + 1];
__device__ int   g_cur[NN];
__device__ int   g_srcs[NE];
__device__ int   g_pos[NE];                 // edge id -> CSR slot
__device__ int   g_bsum[NB];
__device__ int   g_bpre[NB];
__device__ int   g_is64;

__device__ __forceinline__ float lrelu(float x) { return x > 0.f ? x : 0.2f * x; }

__device__ __forceinline__ int edge_val(const void* ei, size_t idx) {
    int v;
    if (g_is64) v = (int)((const long long*)ei)[idx];
    else        v = ((const int*)ei)[idx];
    return min(max(v, 0), NN - 1);
}

// f32x2 packed helpers
__device__ __forceinline__ unsigned long long pk2(float lo, float hi) {
    unsigned long long r;
    asm("mov.b64 %0, {%1, %2};" : "=l"(r) : "r"(__float_as_uint(lo)), "r"(__float_as_uint(hi)));
    return r;
}
__device__ __forceinline__ void upk2(unsigned long long v, float& lo, float& hi) {
    unsigned a, b;
    asm("mov.b64 {%0, %1}, %2;" : "=r"(a), "=r"(b) : "l"(v));
    lo = __uint_as_float(a); hi = __uint_as_float(b);
}
#define FMA2(d, a, b) asm("fma.rn.f32x2 %0, %1, %2, %0;" : "+l"(d) : "l"(a), "l"(b))

// ---------------- dtype detection ----------------
__global__ void k_detect(const int* __restrict__ w) {
    int t = threadIdx.x;
    bool zero = (w[2 * t + 1] == 0);
    __shared__ int cnt;
    if (t == 0) cnt = 0;
    __syncthreads();
    if (!zero) atomicAdd(&cnt, 1);
    __syncthreads();
    if (t == 0) g_is64 = (cnt == 0) ? 1 : 0;
}

// ---------------- CSR build ----------------
__global__ void k_zero() {
    int i = blockIdx.x * blockDim.x + threadIdx.x;
    if (i < NN) g_deg[i] = 0;
}

__global__ void k_count(const void* __restrict__ ei) {
    int e = blockIdx.x * blockDim.x + threadIdx.x;
    if (e < NE) atomicAdd(&g_deg[edge_val(ei, (size_t)NE + e)], 1);
}

__global__ void k_scan1() {
    __shared__ int s[256];
    int t = threadIdx.x;
    int i = blockIdx.x * 256 + t;
    int v = (i < NN) ? g_deg[i] : 0;
    s[t] = v;
    __syncthreads();
    for (int o = 1; o < 256; o <<= 1) {
        int add = 0;
        if (t >= o) add = s[t - o];
        __syncthreads();
        s[t] += add;
        __syncthreads();
    }
    if (i < NN) g_off[i] = s[t];
    if (t == 255) g_bsum[blockIdx.x] = s[255];
}

__global__ void k_scan2() {
    __shared__ int s[256];
    int t = threadIdx.x;
    int v = (t < NB) ? g_bsum[t] : 0;
    s[t] = v;
    __syncthreads();
    for (int o = 1; o < 256; o <<= 1) {
        int add = 0;
        if (t >= o) add = s[t - o];
        __syncthreads();
        s[t] += add;
        __syncthreads();
    }
    if (t < NB) g_bpre[t] = s[t] - v;
}

__global__ void k_scan3() {
    int t = threadIdx.x;
    int i = blockIdx.x * 256 + t;
    if (i < NN) {
        int incl = g_off[i] + g_bpre[blockIdx.x];
        int excl = incl - g_deg[i];
        g_off[i] = excl;
        g_cur[i] = excl;
        if (i == NN - 1) g_off[NN] = incl;
    }
}

__global__ void k_scatter(const void* __restrict__ ei) {
    int e = blockIdx.x * blockDim.x + threadIdx.x;
    if (e < NE) {
        int src = edge_val(ei, e);
        int dst = edge_val(ei, (size_t)NE + e);
        int p = atomicAdd(&g_cur[dst], 1);
        g_srcs[p] = src;
        g_pos[e] = p;
    }
}

// ---------------- GEMM (f32x2) + optional fused attention-logit epilogue ----------------
// sW: [128][128] row-major; sXt: [128 k][66] k-major (transposed X tile).
__device__ __forceinline__ void load_w(float* sW, const float* __restrict__ W,
                                       int ldw, int colbase, int tid) {
#pragma unroll
    for (int i = 0; i < 16; i++) {
        int lin = i * 256 + tid;
        int wr = lin >> 5, wc4 = lin & 31;
        *(float4*)&sW[wr * 128 + wc4 * 4] =
            *(const float4*)&W[(size_t)wr * ldw + colbase + wc4 * 4];
    }
}

__device__ __forceinline__ void load_xt(float* sXt, const float* __restrict__ A,
                                        int M, int r0, int tid) {
#pragma unroll
    for (int i = 0; i < 8; i++) {
        int lin = i * 256 + tid;
        int xr = lin >> 5, xc4 = lin & 31;
        int row = r0 + xr;
        float4 v = make_float4(0.f, 0.f, 0.f, 0.f);
        if (row < M) v = *(const float4*)&A[(size_t)row * 128 + xc4 * 4];
        int k0 = xc4 * 4;
        sXt[(k0 + 0) * 66 + xr] = v.x;
        sXt[(k0 + 1) * 66 + xr] = v.y;
        sXt[(k0 + 2) * 66 + xr] = v.z;
        sXt[(k0 + 3) * 66 + xr] = v.w;
    }
}

// core: 64 rows x 128 cols; thread = rows r0+trow*8..+7 (paired), cols tcol*4..+3
// if asrc != nullptr: also compute attention logits (heads of width C_head cols).
__device__ __forceinline__ void gemm_core(const float* sW, const float* sXt,
                                          float* __restrict__ C, int M, int ldw,
                                          int colbase, int r0, int tid,
                                          const float* __restrict__ asrc,
                                          const float* __restrict__ adst, int C_head) {
    int tcol = tid & 31, trow = tid >> 5;
    unsigned long long accP[4][4];
#pragma unroll
    for (int rp = 0; rp < 4; rp++)
#pragma unroll
        for (int c = 0; c < 4; c++) accP[rp][c] = 0ull;

#pragma unroll 8
    for (int k = 0; k < 128; k++) {
        float4 b = *(const float4*)&sW[k * 128 + tcol * 4];
        unsigned long long bx = pk2(b.x, b.x), by = pk2(b.y, b.y),
                           bz = pk2(b.z, b.z), bw = pk2(b.w, b.w);
        const float2* ap = (const float2*)&sXt[k * 66 + trow * 8];
#pragma unroll
        for (int rp = 0; rp < 4; rp++) {
            float2 a2 = ap[rp];
            unsigned long long aP = pk2(a2.x, a2.y);
            FMA2(accP[rp][0], aP, bx);
            FMA2(accP[rp][1], aP, by);
            FMA2(accP[rp][2], aP, bz);
            FMA2(accP[rp][3], aP, bw);
        }
    }

    float4 av, dv;
    int lph = 0, head = 0;
    if (asrc) {
        av = *(const float4*)&asrc[colbase + tcol * 4];
        dv = *(const float4*)&adst[colbase + tcol * 4];
        lph = C_head >> 2;                       // lanes per head
        head = (colbase + tcol * 4) / C_head;
    }

#pragma unroll
    for (int rp = 0; rp < 4; rp++) {
#pragma unroll
        for (int half = 0; half < 2; half++) {
            float4 v;
            float dum;
            if (half == 0) { upk2(accP[rp][0], v.x, dum); upk2(accP[rp][1], v.y, dum);
                             upk2(accP[rp][2], v.z, dum); upk2(accP[rp][3], v.w, dum); }
            else           { upk2(accP[rp][0], dum, v.x); upk2(accP[rp][1], dum, v.y);
                             upk2(accP[rp][2], dum, v.z); upk2(accP[rp][3], dum, v.w); }
            int row = r0 + trow * 8 + 2 * rp + half;
            if (row < M)
                *(float4*)&C[(size_t)row * ldw + colbase + tcol * 4] = v;
            if (asrc) {
                float ps = v.x * av.x + v.y * av.y + v.z * av.z + v.w * av.w;
                float pd = v.x * dv.x + v.y * dv.y + v.z * dv.z + v.w * dv.w;
#pragma unroll
                for (int o = 8; o > 0; o >>= 1) {
                    if (o < lph) {
                        ps += __shfl_xor_sync(FULLMASK, ps, o);
                        pd += __shfl_xor_sync(FULLMASK, pd, o);
                    }
                }
                if ((tcol & (lph - 1)) == 0 && row < M) {
                    g_as[row * 4 + head] = ps;
                    g_ad[row * 4 + head] = pd;
                }
            }
        }
    }
}

__global__ __launch_bounds__(256) void k_gemm(const float* __restrict__ A,
                                              const float* __restrict__ W,
                                              float* __restrict__ C, int M, int ldw,
                                              const float* __restrict__ asrc,
                                              const float* __restrict__ adst, int C_head) {
    extern __shared__ float sm[];
    float* sW = sm;
    float* sXt = sm + 16384;
    int tid = threadIdx.x;
    int colbase = blockIdx.y * 128;
    int r0 = blockIdx.x * 64;
    load_w(sW, W, ldw, colbase, tid);
    load_xt(sXt, A, M, r0, tid);
    __syncthreads();
    gemm_core(sW, sXt, C, M, ldw, colbase, r0, tid, asrc, adst, C_head);
}

// layer 1: two GEMMs sharing the X tile (W1 -> C1 with attn epilogue, Wskip -> C2)
__global__ __launch_bounds__(256) void k_gemm2(const float* __restrict__ A,
                                               const float* __restrict__ W1,
                                               float* __restrict__ C1,
                                               const float* __restrict__ W2,
                                               float* __restrict__ C2, int M,
                                               const float* __restrict__ asrc,
                                               const float* __restrict__ adst) {
    extern __shared__ float sm[];
    float* sW = sm;
    float* sXt = sm + 16384;
    int tid = threadIdx.x;
    int r0 = blockIdx.x * 64;
    load_w(sW, W1, 128, 0, tid);
    load_xt(sXt, A, M, r0, tid);
    __syncthreads();
    gemm_core(sW, sXt, C1, M, 128, 0, r0, tid, asrc, adst, 32);
    __syncthreads();
    load_w(sW, W2, 128, 0, tid);
    __syncthreads();
    gemm_core(sW, sXt, C2, M, 128, 0, r0, tid, nullptr, nullptr, 0);
}

// ---------------- fused softmax (unnormalized) ----------------
__device__ __forceinline__ void softmax_phase(int beg, int end, int lane, float4 adn,
                                              float4& inv) {
    float4 mx = make_float4(-1e30f, -1e30f, -1e30f, -1e30f);
    for (int j = beg + lane; j < end; j += 32) {
        int s = g_srcs[j];
        float4 a = *(const float4*)&g_as[s * 4];
        mx.x = fmaxf(mx.x, lrelu(a.x + adn.x));
        mx.y = fmaxf(mx.y, lrelu(a.y + adn.y));
        mx.z = fmaxf(mx.z, lrelu(a.z + adn.z));
        mx.w = fmaxf(mx.w, lrelu(a.w + adn.w));
    }
#pragma unroll
    for (int o = 16; o > 0; o >>= 1) {
        mx.x = fmaxf(mx.x, __shfl_xor_sync(FULLMASK, mx.x, o));
        mx.y = fmaxf(mx.y, __shfl_xor_sync(FULLMASK, mx.y, o));
        mx.z = fmaxf(mx.z, __shfl_xor_sync(FULLMASK, mx.z, o));
        mx.w = fmaxf(mx.w, __shfl_xor_sync(FULLMASK, mx.w, o));
    }
    float4 sm = make_float4(0.f, 0.f, 0.f, 0.f);
    float4* EX = (float4*)g_exs;
    for (int j = beg + lane; j < end; j += 32) {
        int s = g_srcs[j];
        float4 a = *(const float4*)&g_as[s * 4];
        float4 ex;
        ex.x = __expf(lrelu(a.x + adn.x) - mx.x);
        ex.y = __expf(lrelu(a.y + adn.y) - mx.y);
        ex.z = __expf(lrelu(a.z + adn.z) - mx.z);
        ex.w = __expf(lrelu(a.w + adn.w) - mx.w);
        EX[j] = ex;
        sm.x += ex.x; sm.y += ex.y; sm.z += ex.z; sm.w += ex.w;
    }
#pragma unroll
    for (int o = 16; o > 0; o >>= 1) {
        sm.x += __shfl_xor_sync(FULLMASK, sm.x, o);
        sm.y += __shfl_xor_sync(FULLMASK, sm.y, o);
        sm.z += __shfl_xor_sync(FULLMASK, sm.z, o);
        sm.w += __shfl_xor_sync(FULLMASK, sm.w, o);
    }
    inv.x = 1.f / (sm.x + 1e-16f);
    inv.y = 1.f / (sm.y + 1e-16f);
    inv.z = 1.f / (sm.z + 1e-16f);
    inv.w = 1.f / (sm.w + 1e-16f);
    __syncwarp();
}

__device__ __forceinline__ float warp_sum(float v) {
#pragma unroll
    for (int o = 16; o > 0; o >>= 1) v += __shfl_xor_sync(FULLMASK, v, o);
    return v;
}

// layers 1/2: 128 channels, epilogue bias+ELU+LN[+skip]
__global__ __launch_bounds__(256) void k_softagg12(const float* __restrict__ feat,
                                                   const float* __restrict__ bias,
                                                   const float* __restrict__ lnw,
                                                   const float* __restrict__ lnb,
                                                   const float* __restrict__ skip,
                                                   const float* __restrict__ bskip,
                                                   float* __restrict__ outp) {
    int n = blockIdx.x * 8 + (threadIdx.x >> 5);
    int lane = threadIdx.x & 31;
    if (n >= NN) return;
    int beg = g_off[n], end = g_off[n + 1];
    float4 adn = *(const float4*)&g_ad[n * 4];
    float4 inv;
    softmax_phase(beg, end, lane, adn, inv);
    if (lane == 0) ((float4*)g_inv)[n] = inv;

    int h = lane >> 3;
    const float4* F = (const float4*)feat;
    float4 acc = make_float4(0.f, 0.f, 0.f, 0.f);
    int j = beg;
    for (; j + 4 <= end; j += 4) {
        int s0 = g_srcs[j], s1 = g_srcs[j + 1], s2 = g_srcs[j + 2], s3 = g_srcs[j + 3];
        float a0 = g_exs[(size_t)j * 4 + h];
        float a1 = g_exs[(size_t)(j + 1) * 4 + h];
        float a2 = g_exs[(size_t)(j + 2) * 4 + h];
        float a3 = g_exs[(size_t)(j + 3) * 4 + h];
        float4 f0 = F[(size_t)s0 * 32 + lane];
        float4 f1 = F[(size_t)s1 * 32 + lane];
        float4 f2 = F[(size_t)s2 * 32 + lane];
        float4 f3 = F[(size_t)s3 * 32 + lane];
        acc.x += a0 * f0.x + a1 * f1.x + a2 * f2.x + a3 * f3.x;
        acc.y += a0 * f0.y + a1 * f1.y + a2 * f2.y + a3 * f3.y;
        acc.z += a0 * f0.z + a1 * f1.z + a2 * f2.z + a3 * f3.z;
        acc.w += a0 * f0.w + a1 * f1.w + a2 * f2.w + a3 * f3.w;
    }
    for (; j < end; j++) {
        int s = g_srcs[j];
        float a = g_exs[(size_t)j * 4 + h];
        float4 f = F[(size_t)s * 32 + lane];
        acc.x += a * f.x; acc.y += a * f.y; acc.z += a * f.z; acc.w += a * f.w;
    }
    float invh = (h == 0) ? inv.x : (h == 1) ? inv.y : (h == 2) ? inv.z : inv.w;
    acc.x *= invh; acc.y *= invh; acc.z *= invh; acc.w *= invh;

    float4 b4 = ((const float4*)bias)[lane];
    float4 v = make_float4(acc.x + b4.x, acc.y + b4.y, acc.z + b4.z, acc.w + b4.w);
    v.x = v.x > 0.f ? v.x : expm1f(v.x);
    v.y = v.y > 0.f ? v.y : expm1f(v.y);
    v.z = v.z > 0.f ? v.z : expm1f(v.z);
    v.w = v.w > 0.f ? v.w : expm1f(v.w);
    float mu = warp_sum(v.x + v.y + v.z + v.w) * (1.f / 128.f);
    float4 d = make_float4(v.x - mu, v.y - mu, v.z - mu, v.w - mu);
    float var = warp_sum(d.x * d.x + d.y * d.y + d.z * d.z + d.w * d.w) * (1.f / 128.f);
    float rstd = rsqrtf(var + 1e-5f);
    float4 w4 = ((const float4*)lnw)[lane];
    float4 lb = ((const float4*)lnb)[lane];
    float4 y = make_float4(d.x * rstd * w4.x + lb.x, d.y * rstd * w4.y + lb.y,
                           d.z * rstd * w4.z + lb.z, d.w * rstd * w4.w + lb.w);
    if (skip) {
        float4 sk = ((const float4*)skip)[(size_t)n * 32 + lane];
        float4 bs = ((const float4*)bskip)[lane];
        y.x += sk.x + bs.x; y.y += sk.y + bs.y; y.z += sk.z + bs.z; y.w += sk.w + bs.w;
    }
    ((float4*)outp)[(size_t)n * 32 + lane] = y;
}

// layer 3: 256 channels, epilogue head-mean + bias -> out[N,64]
__global__ __launch_bounds__(256) void k_softagg3(const float* __restrict__ feat,
                                                  const float* __restrict__ b3,
                                                  float* __restrict__ outp) {
    int n = blockIdx.x * 8 + (threadIdx.x >> 5);
    int lane = threadIdx.x & 31;
    if (n >= NN) return;
    int beg = g_off[n], end = g_off[n + 1];
    float4 adn = *(const float4*)&g_ad[n * 4];
    float4 inv;
    softmax_phase(beg, end, lane, adn, inv);
    if (lane == 0) ((float4*)g_inv)[n] = inv;

    int hlo = lane >> 4;
    const float4* F = (const float4*)feat;
    float4 acc0 = make_float4(0.f, 0.f, 0.f, 0.f);
    float4 acc1 = make_float4(0.f, 0.f, 0.f, 0.f);
    int j = beg;
    for (; j + 2 <= end; j += 2) {
        int s0 = g_srcs[j], s1 = g_srcs[j + 1];
        float al0 = g_exs[(size_t)j * 4 + hlo];
        float ah0 = g_exs[(size_t)j * 4 + 2 + hlo];
        float al1 = g_exs[(size_t)(j + 1) * 4 + hlo];
        float ah1 = g_exs[(size_t)(j + 1) * 4 + 2 + hlo];
        float4 f00 = F[(size_t)s0 * 64 + lane];
        float4 f01 = F[(size_t)s0 * 64 + 32 + lane];
        float4 f10 = F[(size_t)s1 * 64 + lane];
        float4 f11 = F[(size_t)s1 * 64 + 32 + lane];
        acc0.x += al0 * f00.x + al1 * f10.x;
        acc0.y += al0 * f00.y + al1 * f10.y;
        acc0.z += al0 * f00.z + al1 * f10.z;
        acc0.w += al0 * f00.w + al1 * f10.w;
        acc1.x += ah0 * f01.x + ah1 * f11.x;
        acc1.y += ah0 * f01.y + ah1 * f11.y;
        acc1.z += ah0 * f01.z + ah1 * f11.z;
        acc1.w += ah0 * f01.w + ah1 * f11.w;
    }
    for (; j < end; j++) {
        int s = g_srcs[j];
        float al = g_exs[(size_t)j * 4 + hlo];
        float ah = g_exs[(size_t)j * 4 + 2 + hlo];
        float4 f0 = F[(size_t)s * 64 + lane];
        float4 f1 = F[(size_t)s * 64 + 32 + lane];
        acc0.x += al * f0.x; acc0.y += al * f0.y; acc0.z += al * f0.z; acc0.w += al * f0.w;
        acc1.x += ah * f1.x; acc1.y += ah * f1.y; acc1.z += ah * f1.z; acc1.w += ah * f1.w;
    }
    float invlo = hlo ? inv.y : inv.x;
    float invhi = hlo ? inv.w : inv.z;
    acc0.x *= invlo; acc0.y *= invlo; acc0.z *= invlo; acc0.w *= invlo;
    acc1.x *= invhi; acc1.y *= invhi; acc1.z *= invhi; acc1.w *= invhi;

    acc0.x += __shfl_down_sync(FULLMASK, acc0.x, 16);
    acc0.y += __shfl_down_sync(FULLMASK, acc0.y, 16);
    acc0.z += __shfl_down_sync(FULLMASK, acc0.z, 16);
    acc0.w += __shfl_down_sync(FULLMASK, acc0.w, 16);
    acc1.x += __shfl_down_sync(FULLMASK, acc1.x, 16);
    acc1.y += __shfl_down_sync(FULLMASK, acc1.y, 16);
    acc1.z += __shfl_down_sync(FULLMASK, acc1.z, 16);
    acc1.w += __shfl_down_sync(FULLMASK, acc1.w, 16);
    if (lane < 16) {
        float4 bb = ((const float4*)b3)[lane];
        float4 r;
        r.x = (acc0.x + acc1.x) * 0.25f + bb.x;
        r.y = (acc0.y + acc1.y) * 0.25f + bb.y;
        r.z = (acc0.z + acc1.z) * 0.25f + bb.z;
        r.w = (acc0.w + acc1.w) * 0.25f + bb.w;
        ((float4*)outp)[(size_t)n * 16 + lane] = r;
    }
}

// alpha output: alpha[e] = exp_unnorm[pos[e]] * inv[dst[e]]
__global__ void k_alpha(const void* __restrict__ ei, float* __restrict__ alpha_out) {
    int e = blockIdx.x * blockDim.x + threadIdx.x;
    if (e < NE) {
        int p = g_pos[e];
        int dst = edge_val(ei, (size_t)NE + e);
        float4 ex = ((const float4*)g_exs)[p];
        float4 iv = ((const float4*)g_inv)[dst];
        ex.x *= iv.x; ex.y *= iv.y; ex.z *= iv.z; ex.w *= iv.w;
        ((float4*)alpha_out)[e] = ex;
    }
}

// ---------------- host ----------------
extern "C" void kernel_launch(void* const* d_in, const int* in_sizes, int n_in,
                              void* d_out, int out_size) {
    const float* x    = (const float*)d_in[0];
    const void*  ei   = d_in[1];
    const float* W1   = (const float*)d_in[2];
    const float* as1  = (const float*)d_in[3];
    const float* ad1  = (const float*)d_in[4];
    const float* b1   = (const float*)d_in[5];
    const float* ln1w = (const float*)d_in[6];
    const float* ln1b = (const float*)d_in[7];
    const float* Wsk  = (const float*)d_in[8];
    const float* bsk  = (const float*)d_in[9];
    const float* W2   = (const float*)d_in[10];
    const float* as2  = (const float*)d_in[11];
    const float* ad2  = (const float*)d_in[12];
    const float* b2   = (const float*)d_in[13];
    const float* ln2w = (const float*)d_in[14];
    const float* ln2b = (const float*)d_in[15];
    const float* W3   = (const float*)d_in[16];
    const float* as3  = (const float*)d_in[17];
    const float* ad3  = (const float*)d_in[18];
    const float* b3   = (const float*)d_in[19];

    float* out = (float*)d_out;
    float* A1 = out + (size_t)NN * 64;
    float* A2 = A1 + (size_t)NE * 4;
    float* A3 = A2 + (size_t)NE * 4;

    cudaFuncSetAttribute((const void*)k_gemm,
                         cudaFuncAttributeMaxDynamicSharedMemorySize, SMEM_GEMM);
    cudaFuncSetAttribute((const void*)k_gemm2,
                         cudaFuncAttributeMaxDynamicSharedMemorySize, SMEM_GEMM);

    void *ph, *px1, *px2, *psk;
    cudaGetSymbolAddress(&ph, g_h);
    cudaGetSymbolAddress(&px1, g_x1);
    cudaGetSymbolAddress(&px2, g_x2);
    cudaGetSymbolAddress(&psk, g_skip);
    float* fh  = (float*)ph;
    float* fx1 = (float*)px1;
    float* fx2 = (float*)px2;
    float* fsk = (float*)psk;

    // CSR build
    k_detect<<<1, 64>>>((const int*)ei);
    k_zero<<<NB, 256>>>();
    k_count<<<(NE + 255) / 256, 256>>>(ei);
    k_scan1<<<NB, 256>>>();
    k_scan2<<<1, 256>>>();
    k_scan3<<<NB, 256>>>();
    k_scatter<<<(NE + 255) / 256, 256>>>(ei);

    dim3 ggrid((NN + 63) / 64, 1);
    int agrid = (NN + 7) / 8;
    int egrid = (NE + 255) / 256;
    // ---- layer 1 ----
    k_gemm2<<<ggrid, 256, SMEM_GEMM>>>(x, W1, fh, Wsk, fsk, NN, as1, ad1);
    k_softagg12<<<agrid, 256>>>(fh, b1, ln1w, ln1b, fsk, bsk, fx1);
    k_alpha<<<egrid, 256>>>(ei, A1);
    // ---- layer 2 ----
    k_gemm<<<ggrid, 256, SMEM_GEMM>>>(fx1, W2, fh, NN, 128, as2, ad2, 32);
    k_softagg12<<<agrid, 256>>>(fh, b2, ln2w, ln2b, nullptr, nullptr, fx2);
    k_alpha<<<egrid, 256>>>(ei, A2);
    // ---- layer 3 ----
    dim3 ggrid3((NN + 63) / 64, 2);
    k_gemm<<<ggrid3, 256, SMEM_GEMM>>>(fx2, W3, fh, NN, 256, as3, ad3, 64);
    k_softagg3<<<agrid, 256>>>(fh, b3, out);
    k_alpha<<<egrid, 256>>>(ei, A3);
}